// round 9
// baseline (speedup 1.0000x reference)
#include <cuda_runtime.h>
#include <math.h>
#include <stdint.h>

#define B_ 128
#define L_ 512
#define N_ 1023
#define T_ 511
#define D_ 256
#define C_ 511
#define EPS_ 1e-6f

// g_vec is stored in PERMUTED-K layout: within each 32-float k-block,
// float k lives at position p(k) = (k&3)*8 + 2*(k>>3) + ((k>>2)&1).
// This makes tf32 mma fragment loads (k = c4 + 4t) contiguous -> LDS.128.
__device__ float g_vec[(size_t)B_ * N_ * D_];
__device__ float g_WP[512 * 256];     // W packed (perm-k), row 511 zeroed

#define PPW(w) ((((w) & 3) * 8) + 2 * ((w) >> 3) + (((w) >> 2) & 1))
#define PPF(k) (((k) & ~31) + PPW((k) & 31))

__device__ __forceinline__ uint32_t smem_to_u32(const void* p) {
    uint32_t a;
    asm("{ .reg .u64 t; cvta.to.shared.u64 t, %1; cvt.u32.u64 %0, t; }"
        : "=r"(a) : "l"(p));
    return a;
}

// ---------------------------------------------------------------------------
// Zero the node-vector buffer
// ---------------------------------------------------------------------------
__global__ void zero_kernel() {
    size_t total4 = (size_t)B_ * N_ * D_ / 4;
    float4* p = reinterpret_cast<float4*>(g_vec);
    float4 z = make_float4(0.f, 0.f, 0.f, 0.f);
    for (size_t i = (size_t)blockIdx.x * blockDim.x + threadIdx.x; i < total4;
         i += (size_t)gridDim.x * blockDim.x)
        p[i] = z;
}

// ---------------------------------------------------------------------------
// Pack W (C,D) into perm-k layout, zero-padding to 512 rows.
// ---------------------------------------------------------------------------
__global__ void pack_w_kernel(const float* __restrict__ W) {
    int idx = blockIdx.x * 256 + threadIdx.x;   // 512 blocks x 256 = 512*256
    int row = idx >> 8;
    int p   = idx & 255;
    int w   = p & 31;
    int k   = (p & ~31) + 8 * ((w & 7) >> 1) + (w >> 3) + 4 * (w & 1);
    g_WP[idx] = (row < C_) ? W[row * 256 + k] : 0.f;
}

// ---------------------------------------------------------------------------
// Scatter normalized embedding rows into g_vec (perm layout). One warp/leaf.
// ---------------------------------------------------------------------------
__global__ void embed_kernel(const int* __restrict__ leaf_id,
                             const int* __restrict__ mask,
                             const float* __restrict__ emb) {
    int leaf = blockIdx.x * 8 + (threadIdx.x >> 5);
    int lane = threadIdx.x & 31;
    if (leaf >= B_ * L_) return;
    if (mask[leaf] == 0) return;
    int b = leaf / L_;
    int node = leaf_id[2 * leaf + 0];
    int vid  = leaf_id[2 * leaf + 1];
    if ((unsigned)node >= (unsigned)N_) return;
    const float4* src = reinterpret_cast<const float4*>(emb + (size_t)vid * D_);
    float4 v0 = src[lane];
    float4 v1 = src[lane + 32];
    float ss = v0.x * v0.x + v0.y * v0.y + v0.z * v0.z + v0.w * v0.w
             + v1.x * v1.x + v1.y * v1.y + v1.z * v1.z + v1.w * v1.w;
#pragma unroll
    for (int o = 16; o > 0; o >>= 1) ss += __shfl_xor_sync(0xffffffffu, ss, o);
    float inv = 1.f / (sqrtf(ss) + EPS_);
    float* dst = g_vec + ((size_t)b * N_ + node) * D_;
    int k0 = lane * 4;
    dst[PPF(k0 + 0)] = v0.x * inv;
    dst[PPF(k0 + 1)] = v0.y * inv;
    dst[PPF(k0 + 2)] = v0.z * inv;
    dst[PPF(k0 + 3)] = v0.w * inv;
    int k1 = 128 + lane * 4;
    dst[PPF(k1 + 0)] = v1.x * inv;
    dst[PPF(k1 + 1)] = v1.y * inv;
    dst[PPF(k1 + 2)] = v1.z * inv;
    dst[PPF(k1 + 3)] = v1.w * inv;
}

// ---------------------------------------------------------------------------
// Sequential tree composition (R8 logic). One block per batch.
// Thread `tid` owns k-column tid, which lives at gmem offset ppos = PPF(tid).
// All smem correlation logic stays in natural k-space.
// ---------------------------------------------------------------------------
__global__ void __launch_bounds__(256) compose_kernel(const int* __restrict__ comp) {
    __shared__ int sinfo[T_ * 4];
    __shared__ __align__(16) float sa[D_];
    __shared__ float sbw[648];
    __shared__ float pt[4][320];
    __shared__ float red[8];

    int b = blockIdx.x;
    int tid = threadIdx.x;
    float* v = g_vec + (size_t)b * N_ * D_;

    for (int i = tid; i < T_ * 4; i += 256)
        sinfo[i] = comp[(size_t)b * T_ * 4 + i];
    __syncthreads();

    const int t  = tid & 63;
    const int g  = tid >> 6;
    const int t4 = t * 4;
    const int j0 = g * 64;
    const int P0 = (j0 + t4) + ((j0 + t4) >> 2);
    const int ftid = tid + (tid >> 2);
    const int ppos = PPF(tid);

    int typ = sinfo[0], p = sinfo[1], l = sinfo[2], r = sinfo[3];
    float av = v[(size_t)l * D_ + ppos];
    float bv = v[(size_t)r * D_ + ppos];

    for (int ts = 0; ts < T_; ++ts) {
        int typ2 = 0, p2 = 0, l2 = 0, r2 = 0;
        float av2 = 0.f, bv2 = 0.f;
        if (ts + 1 < T_) {
            typ2 = sinfo[4 * ts + 4];
            p2   = sinfo[4 * ts + 5];
            l2   = sinfo[4 * ts + 6];
            r2   = sinfo[4 * ts + 7];
            av2 = v[(size_t)l2 * D_ + ppos];
            bv2 = v[(size_t)r2 * D_ + ppos];
        }

        float outv = 0.f;
        bool wrote = false;
        if (typ == 1) {
            outv = av;
            v[(size_t)p * D_ + ppos] = outv;
            wrote = true;
        } else if (typ == 2) {
            sa[tid] = av;
            int i0 = tid;
            int i1 = tid + 256;
            sbw[i0 + (i0 >> 2)] = bv;
            sbw[i1 + (i1 >> 2)] = bv;
            __syncthreads();

            float w0 = sbw[P0 + 0];
            float w1 = sbw[P0 + 1];
            float w2 = sbw[P0 + 2];
            float w3 = sbw[P0 + 3];
            float a0 = 0.f, a1 = 0.f, a2 = 0.f, a3 = 0.f;
#pragma unroll
            for (int u = 0; u < 16; ++u) {
                float4 aq = *reinterpret_cast<const float4*>(&sa[j0 + 4 * u]);
                int Pu = P0 + 5 * (u + 1);
                a0 += aq.x * w0; a1 += aq.x * w1; a2 += aq.x * w2; a3 += aq.x * w3;
                float n0v = sbw[Pu + 0];
                a0 += aq.y * w1; a1 += aq.y * w2; a2 += aq.y * w3; a3 += aq.y * n0v;
                float n1v = sbw[Pu + 1];
                a0 += aq.z * w2; a1 += aq.z * w3; a2 += aq.z * n0v; a3 += aq.z * n1v;
                float n2v = sbw[Pu + 2];
                a0 += aq.w * w3; a1 += aq.w * n0v; a2 += aq.w * n1v; a3 += aq.w * n2v;
                float n3v = sbw[Pu + 3];
                w0 = n0v; w1 = n1v; w2 = n2v; w3 = n3v;
            }
            pt[g][5 * t + 0] = a0;
            pt[g][5 * t + 1] = a1;
            pt[g][5 * t + 2] = a2;
            pt[g][5 * t + 3] = a3;
            __syncthreads();

            float tot = pt[0][ftid] + pt[1][ftid] + pt[2][ftid] + pt[3][ftid];
            float ss = tot * tot;
#pragma unroll
            for (int o = 16; o > 0; o >>= 1)
                ss += __shfl_xor_sync(0xffffffffu, ss, o);
            if ((tid & 31) == 0) red[tid >> 5] = ss;
            __syncthreads();
            float tss = red[0] + red[1] + red[2] + red[3]
                      + red[4] + red[5] + red[6] + red[7];
            outv = tot / (sqrtf(tss) + EPS_);
            v[(size_t)p * D_ + ppos] = outv;
            wrote = true;
            __syncthreads();
        }

        if (wrote && (ts + 1 < T_)) {
            if (l2 == p) av2 = outv;
            if (r2 == p) bv2 = outv;
        }
        typ = typ2; p = p2; l = l2; r = r2; av = av2; bv = bv2;
    }
}

// ---------------------------------------------------------------------------
// tf32 mma.sync GEMM, CUTLASS sm80 shape:
// BM=BN=128, BK=32, 128 threads = 2x2 warps of 64x64 (32 acc chains/warp).
// Inputs pre-permuted so fragment loads are conflict-free LDS.128.
// cp.async double buffer (R5-style overlap).
// ---------------------------------------------------------------------------
#define GS 36                     // smem row stride in floats
#define STF (256 * GS)            // floats per stage (128 A rows + 128 B rows)

__device__ __forceinline__ void cp16(uint32_t dst, const void* src) {
    asm volatile("cp.async.ca.shared.global [%0], [%1], 16;"
                 :: "r"(dst), "l"(src) : "memory");
}
__device__ __forceinline__ void cp_commit() {
    asm volatile("cp.async.commit_group;" ::: "memory");
}
__device__ __forceinline__ void cp_wait0() {
    asm volatile("cp.async.wait_group 0;" ::: "memory");
}
__device__ __forceinline__ void mma_tf32(float* d, const uint32_t* a,
                                         uint32_t b0, uint32_t b1) {
    asm volatile(
        "mma.sync.aligned.m16n8k8.row.col.f32.tf32.tf32.f32 "
        "{%0,%1,%2,%3}, {%4,%5,%6,%7}, {%8,%9}, {%0,%1,%2,%3};"
        : "+f"(d[0]), "+f"(d[1]), "+f"(d[2]), "+f"(d[3])
        : "r"(a[0]), "r"(a[1]), "r"(a[2]), "r"(a[3]), "r"(b0), "r"(b1));
}

extern __shared__ float gm_smem[];

__global__ void __launch_bounds__(128, 2) gemm_mma_kernel(const float* __restrict__ bias,
                                                          float* __restrict__ out) {
    const float* A = g_vec;
    int tid = threadIdx.x;
    int wid = tid >> 5;
    int lane = tid & 31;
    int qr = lane >> 2;          // 0..7
    int c4 = lane & 3;           // 0..3
    int wm = wid & 1;            // warp m-half (64 rows)
    int wn = wid >> 1;           // warp n-half (64 cols)

    int n0 = blockIdx.x * 128;
    size_t m0 = (size_t)blockIdx.y * 128;

    // loaders: thread owns A row tid and B row tid (32 floats each per stage)
    const float* asrc = A + (m0 + tid) * D_;
    const float* bsrc = g_WP + (size_t)(n0 + tid) * D_;   // n0+tid <= 511
    uint32_t smbase = smem_to_u32(gm_smem);
    uint32_t ldstA = smbase + (uint32_t)(tid * GS) * 4;
    uint32_t ldstB = smbase + (uint32_t)((128 + tid) * GS) * 4;

    // prefetch stage 0
#pragma unroll
    for (int q = 0; q < 8; ++q) {
        cp16(ldstA + q * 16, asrc + q * 4);
        cp16(ldstB + q * 16, bsrc + q * 4);
    }
    cp_commit();

    float acc[4][8][4];
#pragma unroll
    for (int mt = 0; mt < 4; ++mt)
#pragma unroll
        for (int nt = 0; nt < 8; ++nt)
#pragma unroll
            for (int u = 0; u < 4; ++u) acc[mt][nt][u] = 0.f;

    cp_wait0();
    __syncthreads();

    int abase = wm * 64 + qr;
    int bbase = wn * 64 + qr;

    for (int bk = 0; bk < 8; ++bk) {
        int cur = bk & 1;
        if (bk < 7) {
            int nxt = cur ^ 1;
            uint32_t dA = ldstA + (uint32_t)(nxt * STF) * 4;
            uint32_t dB = ldstB + (uint32_t)(nxt * STF) * 4;
            const float* as = asrc + (bk + 1) * 32;
            const float* bs = bsrc + (bk + 1) * 32;
#pragma unroll
            for (int q = 0; q < 8; ++q) {
                cp16(dA + q * 16, as + q * 4);
                cp16(dB + q * 16, bs + q * 4);
            }
            cp_commit();
        }

        const float* sA = gm_smem + cur * STF;
        const float* sB = sA + 128 * GS;
#pragma unroll
        for (int sh = 0; sh < 2; ++sh) {
            float4 aq[4][2];
            float4 bq[8];
#pragma unroll
            for (int mt = 0; mt < 4; ++mt)
#pragma unroll
                for (int h = 0; h < 2; ++h)
                    aq[mt][h] = *reinterpret_cast<const float4*>(
                        &sA[(abase + mt * 16 + h * 8) * GS + c4 * 8 + sh * 4]);
#pragma unroll
            for (int nt = 0; nt < 8; ++nt)
                bq[nt] = *reinterpret_cast<const float4*>(
                    &sB[(bbase + nt * 8) * GS + c4 * 8 + sh * 4]);
#pragma unroll
            for (int sl = 0; sl < 2; ++sl) {
#pragma unroll
                for (int nt = 0; nt < 8; ++nt) {
                    uint32_t b0 = __float_as_uint(sl ? bq[nt].z : bq[nt].x);
                    uint32_t b1 = __float_as_uint(sl ? bq[nt].w : bq[nt].y);
#pragma unroll
                    for (int mt = 0; mt < 4; ++mt) {
                        uint32_t a[4];
                        a[0] = __float_as_uint(sl ? aq[mt][0].z : aq[mt][0].x);
                        a[1] = __float_as_uint(sl ? aq[mt][1].z : aq[mt][1].x);
                        a[2] = __float_as_uint(sl ? aq[mt][0].w : aq[mt][0].y);
                        a[3] = __float_as_uint(sl ? aq[mt][1].w : aq[mt][1].y);
                        mma_tf32(acc[mt][nt], a, b0, b1);
                    }
                }
            }
        }

        if (bk < 7) cp_wait0();
        __syncthreads();
    }

    // epilogue: float2-ish stores with bias (col max = 510 < C_)
#pragma unroll
    for (int mt = 0; mt < 4; ++mt) {
        size_t mrow = m0 + wm * 64 + mt * 16 + qr;
#pragma unroll
        for (int nt = 0; nt < 8; ++nt) {
            int col = n0 + wn * 64 + nt * 8 + 2 * c4;
            bool c1ok = (col + 1) < C_;
            float b0v = bias[col];
            float b1v = c1ok ? bias[col + 1] : 0.f;
            float* o0 = out + mrow * C_ + col;
            o0[0] = acc[mt][nt][0] + b0v;
            if (c1ok) o0[1] = acc[mt][nt][1] + b1v;
            float* o1 = out + (mrow + 8) * C_ + col;
            o1[0] = acc[mt][nt][2] + b0v;
            if (c1ok) o1[1] = acc[mt][nt][3] + b1v;
        }
    }
}

// ---------------------------------------------------------------------------
extern "C" void kernel_launch(void* const* d_in, const int* in_sizes, int n_in,
                              void* d_out, int out_size) {
    const int*   leaf_id = (const int*)d_in[1];    // (B,L,2) int32
    const int*   mask    = (const int*)d_in[2];    // (B,L)   int32
    const int*   comp    = (const int*)d_in[3];    // (B,T,4) int32
    const float* emb     = (const float*)d_in[4];  // (V,D)
    const float* W       = (const float*)d_in[5];  // (C,D)
    const float* bias    = (const float*)d_in[6];  // (C,)
    float* out = (float*)d_out;                    // (B,N,C)

    zero_kernel<<<2048, 256>>>();
    pack_w_kernel<<<512, 256>>>(W);
    embed_kernel<<<(B_ * L_ + 7) / 8, 256>>>(leaf_id, mask, emb);
    compose_kernel<<<B_, 256>>>(comp);

    static bool attr_set = false;
    if (!attr_set) {
        cudaFuncSetAttribute(gemm_mma_kernel,
                             cudaFuncAttributeMaxDynamicSharedMemorySize,
                             2 * STF * 4);
        attr_set = true;
    }
    dim3 grid(4, 1023);   // x = n-tile fastest (A tile L2 reuse), y = m-tile
    gemm_mma_kernel<<<grid, 128, 2 * STF * 4>>>(bias, out);
}

// round 10
// speedup vs baseline: 1.0589x; 1.0589x over previous
#include <cuda_runtime.h>
#include <math.h>
#include <stdint.h>

#define B_ 128
#define L_ 512
#define N_ 1023
#define T_ 511
#define D_ 256
#define C_ 511
#define EPS_ 1e-6f

// 128*1023*256 floats = 134 MB scratch (allocs are forbidden -> device global)
__device__ float g_vec[(size_t)B_ * N_ * D_];

__device__ __forceinline__ uint32_t smem_to_u32(const void* p) {
    uint32_t a;
    asm("{ .reg .u64 t; cvta.to.shared.u64 t, %1; cvt.u32.u64 %0, t; }"
        : "=r"(a) : "l"(p));
    return a;
}

// ---------------------------------------------------------------------------
// Zero the node-vector buffer
// ---------------------------------------------------------------------------
__global__ void zero_kernel() {
    size_t total4 = (size_t)B_ * N_ * D_ / 4;
    float4* p = reinterpret_cast<float4*>(g_vec);
    float4 z = make_float4(0.f, 0.f, 0.f, 0.f);
    for (size_t i = (size_t)blockIdx.x * blockDim.x + threadIdx.x; i < total4;
         i += (size_t)gridDim.x * blockDim.x)
        p[i] = z;
}

// ---------------------------------------------------------------------------
// Scatter normalized embedding rows into g_vec. One warp per leaf.
// ---------------------------------------------------------------------------
__global__ void embed_kernel(const int* __restrict__ leaf_id,
                             const int* __restrict__ mask,
                             const float* __restrict__ emb) {
    int leaf = blockIdx.x * 8 + (threadIdx.x >> 5);
    int lane = threadIdx.x & 31;
    if (leaf >= B_ * L_) return;
    if (mask[leaf] == 0) return;
    int b = leaf / L_;
    int node = leaf_id[2 * leaf + 0];
    int vid  = leaf_id[2 * leaf + 1];
    if ((unsigned)node >= (unsigned)N_) return;
    const float4* src = reinterpret_cast<const float4*>(emb + (size_t)vid * D_);
    float4 v0 = src[lane];
    float4 v1 = src[lane + 32];
    float ss = v0.x * v0.x + v0.y * v0.y + v0.z * v0.z + v0.w * v0.w
             + v1.x * v1.x + v1.y * v1.y + v1.z * v1.z + v1.w * v1.w;
#pragma unroll
    for (int o = 16; o > 0; o >>= 1) ss += __shfl_xor_sync(0xffffffffu, ss, o);
    float inv = 1.f / (sqrtf(ss) + EPS_);
    v0.x *= inv; v0.y *= inv; v0.z *= inv; v0.w *= inv;
    v1.x *= inv; v1.y *= inv; v1.z *= inv; v1.w *= inv;
    float4* dst = reinterpret_cast<float4*>(g_vec + ((size_t)b * N_ + node) * D_);
    dst[lane]      = v0;
    dst[lane + 32] = v1;
}

// ---------------------------------------------------------------------------
// Sequential tree composition, 512 threads (4 warps/SMSP for latency hiding).
// Thread (t = tid&63, g = tid>>6): outputs k = 4t..4t+3, j in [32g, 32g+32),
// rolling 4-register window of b (swizzled phys(i) = i + (i>>2), lane
// stride 5 -> conflict-free). Lower 256 threads stage a, upper 256 stage b.
// ---------------------------------------------------------------------------
__global__ void __launch_bounds__(512) compose_kernel(const int* __restrict__ comp) {
    __shared__ int sinfo[T_ * 4];
    __shared__ __align__(16) float sa[D_];
    __shared__ float sbw[648];
    __shared__ float pt[8][320];
    __shared__ float red[8];

    int b = blockIdx.x;
    int tid = threadIdx.x;
    float* v = g_vec + (size_t)b * N_ * D_;

    for (int i = tid; i < T_ * 4; i += 512)
        sinfo[i] = comp[(size_t)b * T_ * 4 + i];
    __syncthreads();

    const int t  = tid & 63;
    const int g  = tid >> 6;           // 0..7
    const int t4 = t * 4;
    const int j0 = g * 32;
    const int P0 = (j0 + t4) + ((j0 + t4) >> 2);
    const int c  = tid & 255;          // staged column for upper half
    const int ftid = tid + (tid >> 2); // pt column for output k = tid (tid<256)

    for (int ts = 0; ts < T_; ++ts) {
        int typ = sinfo[4 * ts + 0];
        int p   = sinfo[4 * ts + 1];
        int l   = sinfo[4 * ts + 2];
        int r   = sinfo[4 * ts + 3];
        if (typ == 1) {
            if (tid < 256)
                v[(size_t)p * D_ + tid] = v[(size_t)l * D_ + tid];
            __syncthreads();   // make write visible to next step's b-stagers
        } else if (typ == 2) {
            if (tid < 256) {
                sa[tid] = v[(size_t)l * D_ + tid];
            } else {
                float bvv = v[(size_t)r * D_ + c];
                sbw[c + (c >> 2)] = bvv;
                int i1 = c + 256;
                sbw[i1 + (i1 >> 2)] = bvv;
            }
            __syncthreads();

            // rolling window over j in [j0, j0+32)
            float w0 = sbw[P0 + 0];
            float w1 = sbw[P0 + 1];
            float w2 = sbw[P0 + 2];
            float w3 = sbw[P0 + 3];
            float a0 = 0.f, a1 = 0.f, a2 = 0.f, a3 = 0.f;
#pragma unroll
            for (int u = 0; u < 8; ++u) {
                float4 aq = *reinterpret_cast<const float4*>(&sa[j0 + 4 * u]);
                int Pu = P0 + 5 * (u + 1);
                a0 += aq.x * w0; a1 += aq.x * w1; a2 += aq.x * w2; a3 += aq.x * w3;
                float n0v = sbw[Pu + 0];
                a0 += aq.y * w1; a1 += aq.y * w2; a2 += aq.y * w3; a3 += aq.y * n0v;
                float n1v = sbw[Pu + 1];
                a0 += aq.z * w2; a1 += aq.z * w3; a2 += aq.z * n0v; a3 += aq.z * n1v;
                float n2v = sbw[Pu + 2];
                a0 += aq.w * w3; a1 += aq.w * n0v; a2 += aq.w * n1v; a3 += aq.w * n2v;
                float n3v = sbw[Pu + 3];
                w0 = n0v; w1 = n1v; w2 = n2v; w3 = n3v;
            }
            pt[g][5 * t + 0] = a0;
            pt[g][5 * t + 1] = a1;
            pt[g][5 * t + 2] = a2;
            pt[g][5 * t + 3] = a3;
            __syncthreads();

            float tot = 0.f;
            if (tid < 256) {
                tot = pt[0][ftid] + pt[1][ftid] + pt[2][ftid] + pt[3][ftid]
                    + pt[4][ftid] + pt[5][ftid] + pt[6][ftid] + pt[7][ftid];
                float ss = tot * tot;
#pragma unroll
                for (int o = 16; o > 0; o >>= 1)
                    ss += __shfl_xor_sync(0xffffffffu, ss, o);
                if ((tid & 31) == 0) red[tid >> 5] = ss;
            }
            __syncthreads();
            if (tid < 256) {
                float tss = red[0] + red[1] + red[2] + red[3]
                          + red[4] + red[5] + red[6] + red[7];
                v[(size_t)p * D_ + tid] = tot / (sqrtf(tss) + EPS_);
            }
            __syncthreads();   // protect sa/sbw/pt/red + order gmem write
        }
        // typ == 0: exact no-op (reference writes v[b,0] back to itself)
    }
}

// ---------------------------------------------------------------------------
// tf32 mma.sync GEMM (R5 configuration — best measured: 381us, twice).
// BM=128, BN=128, BK=32, 256 threads (8 warps: 4 along M x 2 along N).
// Warp tile 32x64 = 2 x 8 m16n8k8 tiles. cp.async double-buffered smem,
// stride 36 floats (conflict-free frag LDS.32, 16B-aligned rows).
// ---------------------------------------------------------------------------
#define GS 36          // smem row stride in floats
#define STAGE_F (2 * 128 * GS)   // floats per stage (A tile + B tile)

__device__ __forceinline__ void cp16(uint32_t dst, const void* src) {
    asm volatile("cp.async.ca.shared.global [%0], [%1], 16;"
                 :: "r"(dst), "l"(src) : "memory");
}
__device__ __forceinline__ void cp16z(uint32_t dst, const void* src, int srcsz) {
    asm volatile("cp.async.ca.shared.global [%0], [%1], 16, %2;"
                 :: "r"(dst), "l"(src), "r"(srcsz) : "memory");
}
__device__ __forceinline__ void cp_commit() {
    asm volatile("cp.async.commit_group;" ::: "memory");
}
__device__ __forceinline__ void cp_wait0() {
    asm volatile("cp.async.wait_group 0;" ::: "memory");
}
__device__ __forceinline__ void mma_tf32(float* d, const uint32_t* a,
                                         uint32_t b0, uint32_t b1) {
    asm volatile(
        "mma.sync.aligned.m16n8k8.row.col.f32.tf32.tf32.f32 "
        "{%0,%1,%2,%3}, {%4,%5,%6,%7}, {%8,%9}, {%0,%1,%2,%3};"
        : "+f"(d[0]), "+f"(d[1]), "+f"(d[2]), "+f"(d[3])
        : "r"(a[0]), "r"(a[1]), "r"(a[2]), "r"(a[3]), "r"(b0), "r"(b1));
}

extern __shared__ float gm_smem[];

__global__ void __launch_bounds__(256, 2) gemm_mma_kernel(const float* __restrict__ W,
                                                          const float* __restrict__ bias,
                                                          float* __restrict__ out) {
    const float* A = g_vec;
    int tid = threadIdx.x;
    int wid = tid >> 5;
    int lane = tid & 31;
    int qr = lane >> 2;          // 0..7
    int c4 = lane & 3;           // 0..3
    int wm = wid & 3;            // warp row group (32 rows each)
    int wn = wid >> 2;           // warp col group (64 cols each)

    int n0 = blockIdx.x * 128;
    size_t m0 = (size_t)blockIdx.y * 128;

    // loader role: row = tid>>1 (0..127), half = tid&1 -> k offset half*16
    int lrow = tid >> 1;
    int lhalf = tid & 1;
    const float* asrc = A + (m0 + lrow) * D_ + lhalf * 16;
    int brow = n0 + lrow;
    int bok = (brow < C_) ? 16 : 0;
    const float* bsrc = W + (size_t)(bok ? brow : 0) * D_ + lhalf * 16;

    uint32_t smbase = smem_to_u32(gm_smem);
    uint32_t ldstA = smbase + (uint32_t)(lrow * GS + lhalf * 16) * 4;
    uint32_t ldstB = ldstA + 128 * GS * 4;

    // prefetch stage 0 (k0 = 0)
#pragma unroll
    for (int q = 0; q < 4; ++q) {
        cp16(ldstA + q * 16, asrc + q * 4);
        cp16z(ldstB + q * 16, bsrc + q * 4, bok);
    }
    cp_commit();

    float acc[2][8][4];
#pragma unroll
    for (int mt = 0; mt < 2; ++mt)
#pragma unroll
        for (int nt = 0; nt < 8; ++nt)
#pragma unroll
            for (int u = 0; u < 4; ++u) acc[mt][nt][u] = 0.f;

    cp_wait0();
    __syncthreads();

    for (int bk = 0; bk < 8; ++bk) {
        int cur = bk & 1;
        if (bk < 7) {
            int nxt = cur ^ 1;
            uint32_t dA = ldstA + (uint32_t)(nxt * STAGE_F) * 4;
            uint32_t dB = ldstB + (uint32_t)(nxt * STAGE_F) * 4;
            const float* as = asrc + (bk + 1) * 32;
            const float* bs = bsrc + (bk + 1) * 32;
#pragma unroll
            for (int q = 0; q < 4; ++q) {
                cp16(dA + q * 16, as + q * 4);
                cp16z(dB + q * 16, bs + q * 4, bok);
            }
            cp_commit();
        }

        const float* sA = gm_smem + cur * STAGE_F;
        const float* sB = sA + 128 * GS;
        int ra = wm * 32 + qr;
        int nb = wn * 64 + qr;
#pragma unroll
        for (int s = 0; s < 4; ++s) {
            int kb = 8 * s + c4;
            uint32_t af[2][4];
#pragma unroll
            for (int mt = 0; mt < 2; ++mt) {
                int r0 = ra + mt * 16;
                af[mt][0] = __float_as_uint(sA[r0 * GS + kb]);
                af[mt][1] = __float_as_uint(sA[(r0 + 8) * GS + kb]);
                af[mt][2] = __float_as_uint(sA[r0 * GS + kb + 4]);
                af[mt][3] = __float_as_uint(sA[(r0 + 8) * GS + kb + 4]);
            }
#pragma unroll
            for (int nt = 0; nt < 8; ++nt) {
                int n = nb + nt * 8;
                uint32_t b0 = __float_as_uint(sB[n * GS + kb]);
                uint32_t b1 = __float_as_uint(sB[n * GS + kb + 4]);
                mma_tf32(acc[0][nt], af[0], b0, b1);
                mma_tf32(acc[1][nt], af[1], b0, b1);
            }
        }

        if (bk < 7) cp_wait0();
        __syncthreads();
    }

    // epilogue: direct stores with bias
#pragma unroll
    for (int nt = 0; nt < 8; ++nt) {
        int col = n0 + wn * 64 + nt * 8 + 2 * c4;
        if (col >= C_) continue;
        bool c1ok = (col + 1) < C_;
        float b0v = bias[col];
        float b1v = c1ok ? bias[col + 1] : 0.f;
#pragma unroll
        for (int mt = 0; mt < 2; ++mt) {
            size_t m = m0 + wm * 32 + mt * 16 + qr;
            float* o0 = out + m * C_ + col;
            o0[0] = acc[mt][nt][0] + b0v;
            if (c1ok) o0[1] = acc[mt][nt][1] + b1v;
            float* o1 = out + (m + 8) * C_ + col;
            o1[0] = acc[mt][nt][2] + b0v;
            if (c1ok) o1[1] = acc[mt][nt][3] + b1v;
        }
    }
}

// ---------------------------------------------------------------------------
extern "C" void kernel_launch(void* const* d_in, const int* in_sizes, int n_in,
                              void* d_out, int out_size) {
    const int*   leaf_id = (const int*)d_in[1];    // (B,L,2) int32
    const int*   mask    = (const int*)d_in[2];    // (B,L)   int32
    const int*   comp    = (const int*)d_in[3];    // (B,T,4) int32
    const float* emb     = (const float*)d_in[4];  // (V,D)
    const float* W       = (const float*)d_in[5];  // (C,D)
    const float* bias    = (const float*)d_in[6];  // (C,)
    float* out = (float*)d_out;                    // (B,N,C)

    zero_kernel<<<2048, 256>>>();
    embed_kernel<<<(B_ * L_ + 7) / 8, 256>>>(leaf_id, mask, emb);
    compose_kernel<<<B_, 512>>>(comp);

    static bool attr_set = false;
    if (!attr_set) {
        cudaFuncSetAttribute(gemm_mma_kernel,
                             cudaFuncAttributeMaxDynamicSharedMemorySize,
                             2 * STAGE_F * 4);
        attr_set = true;
    }
    dim3 grid(4, 1023);   // x = n-tile fastest (A tile L2 reuse), y = m-tile
    gemm_mma_kernel<<<grid, 256, 2 * STAGE_F * 4>>>(W, bias, out);
}

// round 11
// speedup vs baseline: 1.2689x; 1.1983x over previous
#include <cuda_runtime.h>
#include <cuda_fp16.h>
#include <math.h>
#include <stdint.h>

#define B_ 128
#define L_ 512
#define N_ 1023
#define T_ 511
#define D_ 256
#define C_ 511
#define EPS_ 1e-6f

// fp32 master copy (compose iterates on this) + fp16 mirror for the GEMM.
__device__ float  g_vec[(size_t)B_ * N_ * D_];     // 134 MB
__device__ __half g_vec16[(size_t)B_ * N_ * D_];   // 67 MB
__device__ __half g_W16[512 * 256];                // W fp16, zero-padded row 511

__device__ __forceinline__ uint32_t smem_to_u32(const void* p) {
    uint32_t a;
    asm("{ .reg .u64 t; cvta.to.shared.u64 t, %1; cvt.u32.u64 %0, t; }"
        : "=r"(a) : "l"(p));
    return a;
}

// ---------------------------------------------------------------------------
// Zero both node-vector buffers
// ---------------------------------------------------------------------------
__global__ void zero_kernel() {
    size_t t32 = (size_t)B_ * N_ * D_ / 4;        // float4 count
    float4* p = reinterpret_cast<float4*>(g_vec);
    float4 z = make_float4(0.f, 0.f, 0.f, 0.f);
    for (size_t i = (size_t)blockIdx.x * blockDim.x + threadIdx.x; i < t32;
         i += (size_t)gridDim.x * blockDim.x)
        p[i] = z;
    size_t t16 = (size_t)B_ * N_ * D_ / 8;        // uint4 over halfs
    uint4* q = reinterpret_cast<uint4*>(g_vec16);
    uint4 zz = make_uint4(0u, 0u, 0u, 0u);
    for (size_t i = (size_t)blockIdx.x * blockDim.x + threadIdx.x; i < t16;
         i += (size_t)gridDim.x * blockDim.x)
        q[i] = zz;
}

// ---------------------------------------------------------------------------
// Pack W (C,D) fp32 -> fp16, zero-padding to 512 rows.
// ---------------------------------------------------------------------------
__global__ void pack_w_kernel(const float* __restrict__ W) {
    int idx = blockIdx.x * 256 + threadIdx.x;      // 512*256 total
    int row = idx >> 8;
    int k   = idx & 255;
    g_W16[idx] = __float2half((row < C_) ? W[row * 256 + k] : 0.f);
}

// ---------------------------------------------------------------------------
// Scatter normalized embedding rows into g_vec + g_vec16. One warp per leaf.
// ---------------------------------------------------------------------------
__global__ void embed_kernel(const int* __restrict__ leaf_id,
                             const int* __restrict__ mask,
                             const float* __restrict__ emb) {
    int leaf = blockIdx.x * 8 + (threadIdx.x >> 5);
    int lane = threadIdx.x & 31;
    if (leaf >= B_ * L_) return;
    if (mask[leaf] == 0) return;
    int b = leaf / L_;
    int node = leaf_id[2 * leaf + 0];
    int vid  = leaf_id[2 * leaf + 1];
    if ((unsigned)node >= (unsigned)N_) return;
    const float4* src = reinterpret_cast<const float4*>(emb + (size_t)vid * D_);
    float4 v0 = src[lane];
    float4 v1 = src[lane + 32];
    float ss = v0.x * v0.x + v0.y * v0.y + v0.z * v0.z + v0.w * v0.w
             + v1.x * v1.x + v1.y * v1.y + v1.z * v1.z + v1.w * v1.w;
#pragma unroll
    for (int o = 16; o > 0; o >>= 1) ss += __shfl_xor_sync(0xffffffffu, ss, o);
    float inv = 1.f / (sqrtf(ss) + EPS_);
    v0.x *= inv; v0.y *= inv; v0.z *= inv; v0.w *= inv;
    v1.x *= inv; v1.y *= inv; v1.z *= inv; v1.w *= inv;
    size_t base = ((size_t)b * N_ + node) * D_;
    float4* dst = reinterpret_cast<float4*>(g_vec + base);
    dst[lane]      = v0;
    dst[lane + 32] = v1;
    __half2* dst16 = reinterpret_cast<__half2*>(g_vec16 + base);
    dst16[2 * lane + 0]  = __float22half2_rn(make_float2(v0.x, v0.y));
    dst16[2 * lane + 1]  = __float22half2_rn(make_float2(v0.z, v0.w));
    dst16[2 * lane + 64] = __float22half2_rn(make_float2(v1.x, v1.y));
    dst16[2 * lane + 65] = __float22half2_rn(make_float2(v1.z, v1.w));
}

// ---------------------------------------------------------------------------
// Sequential tree composition (R8 structure — best measured) + fp16 mirror.
// One block per batch; cross-step operand prefetch with register hazard patch.
// ---------------------------------------------------------------------------
__global__ void __launch_bounds__(256) compose_kernel(const int* __restrict__ comp) {
    __shared__ int sinfo[T_ * 4];
    __shared__ __align__(16) float sa[D_];
    __shared__ float sbw[648];
    __shared__ float pt[4][320];
    __shared__ float red[8];

    int b = blockIdx.x;
    int tid = threadIdx.x;
    float*  v   = g_vec   + (size_t)b * N_ * D_;
    __half* v16 = g_vec16 + (size_t)b * N_ * D_;

    for (int i = tid; i < T_ * 4; i += 256)
        sinfo[i] = comp[(size_t)b * T_ * 4 + i];
    __syncthreads();

    const int t  = tid & 63;
    const int g  = tid >> 6;
    const int t4 = t * 4;
    const int j0 = g * 64;
    const int P0 = (j0 + t4) + ((j0 + t4) >> 2);
    const int ftid = tid + (tid >> 2);

    int typ = sinfo[0], p = sinfo[1], l = sinfo[2], r = sinfo[3];
    float av = v[(size_t)l * D_ + tid];
    float bv = v[(size_t)r * D_ + tid];

    for (int ts = 0; ts < T_; ++ts) {
        int typ2 = 0, p2 = 0, l2 = 0, r2 = 0;
        float av2 = 0.f, bv2 = 0.f;
        if (ts + 1 < T_) {
            typ2 = sinfo[4 * ts + 4];
            p2   = sinfo[4 * ts + 5];
            l2   = sinfo[4 * ts + 6];
            r2   = sinfo[4 * ts + 7];
            av2 = v[(size_t)l2 * D_ + tid];
            bv2 = v[(size_t)r2 * D_ + tid];
        }

        float outv = 0.f;
        bool wrote = false;
        if (typ == 1) {
            outv = av;
            v[(size_t)p * D_ + tid] = outv;
            v16[(size_t)p * D_ + tid] = __float2half(outv);
            wrote = true;
        } else if (typ == 2) {
            sa[tid] = av;
            int i0 = tid;
            int i1 = tid + 256;
            sbw[i0 + (i0 >> 2)] = bv;
            sbw[i1 + (i1 >> 2)] = bv;
            __syncthreads();

            float w0 = sbw[P0 + 0];
            float w1 = sbw[P0 + 1];
            float w2 = sbw[P0 + 2];
            float w3 = sbw[P0 + 3];
            float a0 = 0.f, a1 = 0.f, a2 = 0.f, a3 = 0.f;
#pragma unroll
            for (int u = 0; u < 16; ++u) {
                float4 aq = *reinterpret_cast<const float4*>(&sa[j0 + 4 * u]);
                int Pu = P0 + 5 * (u + 1);
                a0 += aq.x * w0; a1 += aq.x * w1; a2 += aq.x * w2; a3 += aq.x * w3;
                float n0v = sbw[Pu + 0];
                a0 += aq.y * w1; a1 += aq.y * w2; a2 += aq.y * w3; a3 += aq.y * n0v;
                float n1v = sbw[Pu + 1];
                a0 += aq.z * w2; a1 += aq.z * w3; a2 += aq.z * n0v; a3 += aq.z * n1v;
                float n2v = sbw[Pu + 2];
                a0 += aq.w * w3; a1 += aq.w * n0v; a2 += aq.w * n1v; a3 += aq.w * n2v;
                float n3v = sbw[Pu + 3];
                w0 = n0v; w1 = n1v; w2 = n2v; w3 = n3v;
            }
            pt[g][5 * t + 0] = a0;
            pt[g][5 * t + 1] = a1;
            pt[g][5 * t + 2] = a2;
            pt[g][5 * t + 3] = a3;
            __syncthreads();

            float tot = pt[0][ftid] + pt[1][ftid] + pt[2][ftid] + pt[3][ftid];
            float ss = tot * tot;
#pragma unroll
            for (int o = 16; o > 0; o >>= 1)
                ss += __shfl_xor_sync(0xffffffffu, ss, o);
            if ((tid & 31) == 0) red[tid >> 5] = ss;
            __syncthreads();
            float tss = red[0] + red[1] + red[2] + red[3]
                      + red[4] + red[5] + red[6] + red[7];
            outv = tot / (sqrtf(tss) + EPS_);
            v[(size_t)p * D_ + tid] = outv;
            v16[(size_t)p * D_ + tid] = __float2half(outv);
            wrote = true;
            __syncthreads();
        }

        if (wrote && (ts + 1 < T_)) {
            if (l2 == p) av2 = outv;
            if (r2 == p) bv2 = outv;
        }
        typ = typ2; p = p2; l = l2; r = r2; av = av2; bv = bv2;
    }
}

// ---------------------------------------------------------------------------
// fp16 mma.sync m16n8k16 GEMM: half the HMMA instructions of the tf32 path.
// BM=128, BN=128, BK=32, 256 threads (8 warps: 4 along M x 2 along N).
// Warp tile 32x64 = 2 x 8 mma tiles x 2 k-steps. cp.async double buffer.
// ---------------------------------------------------------------------------
#define GS_H 40                      // smem row stride in halfs (32 + 8 pad)
#define STAGE_H (256 * GS_H)         // halfs per stage (128 A rows + 128 B rows)

__device__ __forceinline__ void cp16(uint32_t dst, const void* src) {
    asm volatile("cp.async.ca.shared.global [%0], [%1], 16;"
                 :: "r"(dst), "l"(src) : "memory");
}
__device__ __forceinline__ void cp_commit() {
    asm volatile("cp.async.commit_group;" ::: "memory");
}
__device__ __forceinline__ void cp_wait0() {
    asm volatile("cp.async.wait_group 0;" ::: "memory");
}
__device__ __forceinline__ void mma_f16(float* d, const uint32_t* a,
                                        uint32_t b0, uint32_t b1) {
    asm volatile(
        "mma.sync.aligned.m16n8k16.row.col.f32.f16.f16.f32 "
        "{%0,%1,%2,%3}, {%4,%5,%6,%7}, {%8,%9}, {%0,%1,%2,%3};"
        : "+f"(d[0]), "+f"(d[1]), "+f"(d[2]), "+f"(d[3])
        : "r"(a[0]), "r"(a[1]), "r"(a[2]), "r"(a[3]), "r"(b0), "r"(b1));
}

extern __shared__ __half gm_smem[];

__global__ void __launch_bounds__(256, 2) gemm_mma_kernel(const float* __restrict__ bias,
                                                          float* __restrict__ out) {
    const __half* A = g_vec16;
    int tid = threadIdx.x;
    int wid = tid >> 5;
    int lane = tid & 31;
    int qr = lane >> 2;          // 0..7
    int c4 = lane & 3;           // 0..3
    int wm = wid & 3;            // warp row group (32 rows each)
    int wn = wid >> 2;           // warp col group (64 cols each)

    int n0 = blockIdx.x * 128;
    size_t m0 = (size_t)blockIdx.y * 128;

    // loader: row = tid>>1 (0..127), half-seg = tid&1 -> halfs [seg*16, +16)
    int lrow = tid >> 1;
    int lseg = tid & 1;
    const __half* asrc = A + (m0 + lrow) * D_ + lseg * 16;
    const __half* bsrc = g_W16 + (size_t)(n0 + lrow) * D_ + lseg * 16;  // padded

    uint32_t smbase = smem_to_u32(gm_smem);
    uint32_t ldstA = smbase + (uint32_t)(lrow * GS_H + lseg * 16) * 2;
    uint32_t ldstB = ldstA + 128 * GS_H * 2;

    // prefetch stage 0
#pragma unroll
    for (int q = 0; q < 2; ++q) {
        cp16(ldstA + q * 16, asrc + q * 8);
        cp16(ldstB + q * 16, bsrc + q * 8);
    }
    cp_commit();

    float acc[2][8][4];
#pragma unroll
    for (int mt = 0; mt < 2; ++mt)
#pragma unroll
        for (int nt = 0; nt < 8; ++nt)
#pragma unroll
            for (int u = 0; u < 4; ++u) acc[mt][nt][u] = 0.f;

    cp_wait0();
    __syncthreads();

    for (int bk = 0; bk < 8; ++bk) {
        int cur = bk & 1;
        if (bk < 7) {
            int nxt = cur ^ 1;
            uint32_t dA = ldstA + (uint32_t)(nxt * STAGE_H) * 2;
            uint32_t dB = ldstB + (uint32_t)(nxt * STAGE_H) * 2;
            const __half* as = asrc + (bk + 1) * 32;
            const __half* bs = bsrc + (bk + 1) * 32;
#pragma unroll
            for (int q = 0; q < 2; ++q) {
                cp16(dA + q * 16, as + q * 8);
                cp16(dB + q * 16, bs + q * 8);
            }
            cp_commit();
        }

        const __half* sA = gm_smem + cur * STAGE_H;
        const __half* sB = sA + 128 * GS_H;
        int ra = wm * 32 + qr;
        int nb = wn * 64 + qr;
#pragma unroll
        for (int s = 0; s < 2; ++s) {
            int kb = 16 * s + 2 * c4;        // half index of this thread's k-pair
            uint32_t af[2][4];
#pragma unroll
            for (int mt = 0; mt < 2; ++mt) {
                int r0 = ra + mt * 16;
                af[mt][0] = *reinterpret_cast<const uint32_t*>(&sA[r0 * GS_H + kb]);
                af[mt][1] = *reinterpret_cast<const uint32_t*>(&sA[(r0 + 8) * GS_H + kb]);
                af[mt][2] = *reinterpret_cast<const uint32_t*>(&sA[r0 * GS_H + kb + 8]);
                af[mt][3] = *reinterpret_cast<const uint32_t*>(&sA[(r0 + 8) * GS_H + kb + 8]);
            }
#pragma unroll
            for (int nt = 0; nt < 8; ++nt) {
                int n = nb + nt * 8;
                uint32_t b0 = *reinterpret_cast<const uint32_t*>(&sB[n * GS_H + kb]);
                uint32_t b1 = *reinterpret_cast<const uint32_t*>(&sB[n * GS_H + kb + 8]);
                mma_f16(acc[0][nt], af[0], b0, b1);
                mma_f16(acc[1][nt], af[1], b0, b1);
            }
        }

        if (bk < 7) cp_wait0();
        __syncthreads();
    }

    // epilogue: direct stores with bias
#pragma unroll
    for (int nt = 0; nt < 8; ++nt) {
        int col = n0 + wn * 64 + nt * 8 + 2 * c4;
        if (col >= C_) continue;
        bool c1ok = (col + 1) < C_;
        float b0v = bias[col];
        float b1v = c1ok ? bias[col + 1] : 0.f;
#pragma unroll
        for (int mt = 0; mt < 2; ++mt) {
            size_t m = m0 + wm * 32 + mt * 16 + qr;
            float* o0 = out + m * C_ + col;
            o0[0] = acc[mt][nt][0] + b0v;
            if (c1ok) o0[1] = acc[mt][nt][1] + b1v;
            float* o1 = out + (m + 8) * C_ + col;
            o1[0] = acc[mt][nt][2] + b0v;
            if (c1ok) o1[1] = acc[mt][nt][3] + b1v;
        }
    }
}

// ---------------------------------------------------------------------------
extern "C" void kernel_launch(void* const* d_in, const int* in_sizes, int n_in,
                              void* d_out, int out_size) {
    const int*   leaf_id = (const int*)d_in[1];    // (B,L,2) int32
    const int*   mask    = (const int*)d_in[2];    // (B,L)   int32
    const int*   comp    = (const int*)d_in[3];    // (B,T,4) int32
    const float* emb     = (const float*)d_in[4];  // (V,D)
    const float* W       = (const float*)d_in[5];  // (C,D)
    const float* bias    = (const float*)d_in[6];  // (C,)
    float* out = (float*)d_out;                    // (B,N,C)

    zero_kernel<<<2048, 256>>>();
    pack_w_kernel<<<512, 256>>>(W);
    embed_kernel<<<(B_ * L_ + 7) / 8, 256>>>(leaf_id, mask, emb);
    compose_kernel<<<B_, 256>>>(comp);

    static bool attr_set = false;
    if (!attr_set) {
        cudaFuncSetAttribute(gemm_mma_kernel,
                             cudaFuncAttributeMaxDynamicSharedMemorySize,
                             2 * STAGE_H * 2);
        attr_set = true;
    }
    dim3 grid(4, 1023);   // x = n-tile fastest (A tile L2 reuse), y = m-tile
    gemm_mma_kernel<<<grid, 256, 2 * STAGE_H * 2>>>(bias, out);
}